// round 10
// baseline (speedup 1.0000x reference)
#include <cuda_runtime.h>
#include <cstdint>

#define B_ 16
#define S_ 8192
#define H_ 512
#define P_ 32
#define NSPLIT 8
#define TS 512          // s-rows per tile
#define KC 8            // h per k-chunk
#define NCH (H_/KC)     // 64 chunks
#define PSTR 516        // probe smem row stride (floats) -> conflict-free
#define XSTR 12         // x-stage row stride (floats)    -> conflict-free
#define SSTR 513        // score-stage row stride

// 16 MB scratch for scores[b*P+p][s]
__device__ float g_scores[(size_t)B_ * P_ * S_];

// ---------------- helpers ----------------
__device__ __forceinline__ void ffma2(unsigned long long& d, unsigned long long a,
                                      unsigned long long b) {
    asm("fma.rn.f32x2 %0, %1, %2, %0;" : "+l"(d) : "l"(a), "l"(b));
}
__device__ __forceinline__ float2 unpk(unsigned long long v) {
    float2 r;
    asm("mov.b64 {%0,%1}, %2;" : "=f"(r.x), "=f"(r.y) : "l"(v));
    return r;
}
__device__ __forceinline__ void cp16(float* s, const float* g) {
    unsigned sa = (unsigned)__cvta_generic_to_shared(s);
    asm volatile("cp.async.cg.shared.global [%0], [%1], 16;" :: "r"(sa), "l"(g));
}
__device__ __forceinline__ void cp_commit() { asm volatile("cp.async.commit_group;"); }
template <int N>
__device__ __forceinline__ void cp_wait() { asm volatile("cp.async.wait_group %0;" :: "n"(N)); }

// ---------------- kernel 1: scores = probes @ x^T (fp32, packed f32x2) ----------------
// grid = B_*NSPLIT (=128), block = 256. Each CTA: 1024 s-rows in 2 tiles of 512.
// Thread tile 8s x 8p: s = rowt + 64*i, p = col + 4*j (col = t&3, rowt = t>>2).
__global__ void __launch_bounds__(256, 1)
k_scores(const float* __restrict__ x, const float* __restrict__ probes) {
    extern __shared__ float sm[];
    float* psm = sm;                     // P_*PSTR   = 16512 f
    float* stg = sm + P_ * PSTR;         // 2*TS*XSTR = 12288 f
    float* scs = stg + 2 * TS * XSTR;    // P_*SSTR   = 16416 f

    const int t = threadIdx.x;
    const int col = t & 3;
    const int rowt = t >> 2;
    const int b = blockIdx.x >> 3;
    const int split = blockIdx.x & 7;
    const float* xb = x + (size_t)b * S_ * H_;

    // probes -> smem (padded rows)
    for (int idx = t; idx < P_ * H_; idx += 256) {
        psm[(idx >> 9) * PSTR + (idx & 511)] = probes[idx];
    }

    for (int tile = 0; tile < 2; ++tile) {
        const int s0 = split * 1024 + tile * TS;

        unsigned long long acc[8][8];
#pragma unroll
        for (int i = 0; i < 8; ++i)
#pragma unroll
            for (int j = 0; j < 8; ++j) acc[i][j] = 0ull;

        // prologue: chunk 0 -> buf 0
        {
#pragma unroll
            for (int q = 0; q < 4; ++q) {
                int idx = t + 256 * q;
                int row = idx >> 1, seg = (idx & 1) * 4;
                cp16(stg + row * XSTR + seg, xb + (size_t)(s0 + row) * H_ + seg);
            }
            cp_commit();
        }

#pragma unroll 1
        for (int c = 0; c < NCH; ++c) {
            if (c + 1 < NCH) {
                float* dst = stg + ((c + 1) & 1) * TS * XSTR;
                const int hc1 = (c + 1) * KC;
#pragma unroll
                for (int q = 0; q < 4; ++q) {
                    int idx = t + 256 * q;
                    int row = idx >> 1, seg = (idx & 1) * 4;
                    cp16(dst + row * XSTR + seg, xb + (size_t)(s0 + row) * H_ + hc1 + seg);
                }
                cp_commit();
                cp_wait<1>();
            } else {
                cp_wait<0>();
            }
            __syncthreads();

            const float* st = stg + (c & 1) * TS * XSTR;
            const int hc = c * KC;
#pragma unroll
            for (int u = 0; u < 2; ++u) {
                ulonglong2 pvv[8];
#pragma unroll
                for (int j = 0; j < 8; ++j)
                    pvv[j] = *(const ulonglong2*)&psm[(col + 4 * j) * PSTR + hc + u * 4];
#pragma unroll
                for (int i = 0; i < 8; ++i) {
                    ulonglong2 xv = *(const ulonglong2*)&st[(rowt + 64 * i) * XSTR + u * 4];
#pragma unroll
                    for (int j = 0; j < 8; ++j) {
                        ffma2(acc[i][j], xv.x, pvv[j].x);
                        ffma2(acc[i][j], xv.y, pvv[j].y);
                    }
                }
            }
            __syncthreads();
        }

        // finalize (even+odd partials) and stage for coalesced store
#pragma unroll
        for (int j = 0; j < 8; ++j)
#pragma unroll
            for (int i = 0; i < 8; ++i) {
                float2 v = unpk(acc[i][j]);
                scs[(col + 4 * j) * SSTR + rowt + 64 * i] = v.x + v.y;
            }
        __syncthreads();

        float* grow = g_scores + (size_t)(b * P_) * S_ + s0;
        for (int idx = t; idx < P_ * TS; idx += 256) {
            int p = idx >> 9;
            int sl = idx & 511;
            grow[(size_t)p * S_ + sl] = scs[p * SSTR + sl];
        }
        __syncthreads();
    }
}

// ---------------- kernel 2: exact softmax stats + sparse context gather ----------------
// grid = B_*P_ (=512), block = 256. One CTA per (b,p).
// Exact max and exact denominator over all 8192 scores; numerator gathers only
// entries with score >= max-20 (skipped mass < 2e-5, far below 1e-3 tolerance).
__global__ void __launch_bounds__(256, 2)
k_softmax_ctx(const float* __restrict__ x, float* __restrict__ out) {
    extern __shared__ float sm2[];
    float* ssc = sm2;                    // 8192 scores
    float* lw  = sm2 + 8192;             // weights of kept entries
    int*   lst = (int*)(sm2 + 16384);    // s-indices of kept entries (cap 8192: safe)

    __shared__ float red[8];
    __shared__ float Msh, Lsh;
    __shared__ int cnt;

    const int t = threadIdx.x;
    const int bp = blockIdx.x;
    const int b = bp >> 5;
    const int p = bp & 31;
    const float* srow = g_scores + (size_t)bp * S_;

    for (int idx = t; idx < S_ / 4; idx += 256)
        ((float4*)ssc)[idx] = ((const float4*)srow)[idx];
    if (t == 0) cnt = 0;
    __syncthreads();

    // block max
    float m = -3.4e38f;
    for (int i = t; i < S_; i += 256) m = fmaxf(m, ssc[i]);
#pragma unroll
    for (int o = 16; o; o >>= 1) m = fmaxf(m, __shfl_xor_sync(0xffffffffu, m, o));
    if ((t & 31) == 0) red[t >> 5] = m;
    __syncthreads();
    if (t == 0) {
        float mm = red[0];
#pragma unroll
        for (int w = 1; w < 8; ++w) mm = fmaxf(mm, red[w]);
        Msh = mm;
    }
    __syncthreads();
    const float M = Msh;
    const float thr = M - 20.0f;

    // exact denominator + gather significant entries
    float ls = 0.f;
    for (int i = t; i < S_; i += 256) {
        float sc = ssc[i];
        float w = __expf(sc - M);
        ls += w;
        if (sc >= thr) {
            int k = atomicAdd(&cnt, 1);
            lst[k] = i;
            lw[k] = w;
        }
    }
#pragma unroll
    for (int o = 16; o; o >>= 1) ls += __shfl_xor_sync(0xffffffffu, ls, o);
    if ((t & 31) == 0) red[t >> 5] = ls;
    __syncthreads();
    if (t == 0) {
        float s = 0.f;
#pragma unroll
        for (int w = 0; w < 8; ++w) s += red[w];
        Lsh = s;
    }
    __syncthreads();
    const float inv = 1.0f / Lsh;
    const int n = cnt;

    // sparse context: each thread owns h = 2t, 2t+1
    const float* xb = x + (size_t)b * S_ * H_ + (t * 2);
    float a0 = 0.f, a1 = 0.f;
    for (int e = 0; e < n; ++e) {
        float2 v = *(const float2*)(xb + (size_t)lst[e] * H_);
        float w = lw[e];
        a0 += w * v.x;
        a1 += w * v.y;
    }
    const size_t o0 = (size_t)b * (P_ * H_) + (size_t)p * H_ + t * 2;
    out[o0]     = a0 * inv;
    out[o0 + 1] = a1 * inv;
}

// ---------------- launch ----------------
extern "C" void kernel_launch(void* const* d_in, const int* in_sizes, int n_in,
                              void* d_out, int out_size) {
    const float* x = (const float*)d_in[0];       // [B,S,H] f32
    const float* probes = (const float*)d_in[1];  // [P,H]  f32
    float* out = (float*)d_out;                   // [B, P*H] f32

    const int smem1 = (P_ * PSTR + 2 * TS * XSTR + P_ * SSTR) * (int)sizeof(float); // 180864
    const int smem2 = (S_ * 3) * (int)sizeof(float);                                // 98304

    cudaFuncSetAttribute(k_scores, cudaFuncAttributeMaxDynamicSharedMemorySize, smem1);
    cudaFuncSetAttribute(k_softmax_ctx, cudaFuncAttributeMaxDynamicSharedMemorySize, smem2);

    k_scores<<<B_ * NSPLIT, 256, smem1>>>(x, probes);
    k_softmax_ctx<<<B_ * P_, 256, smem2>>>(x, out);
}